// round 9
// baseline (speedup 1.0000x reference)
#include <cuda_runtime.h>

#define DIM     1024
#define NPAIRS  512
#define NLAYER  10
#define NACTIVE 2044   // params for layers 1..9: 2*sum(DIM>>l, l=1..9)
#define CTAS    740    // 5 CTAs/SM * 148 SMs — one persistent wave at 48 regs

// Single persistent kernel.
//
// Math: with base point 0 both Mobius maps are radial scalings
//   log0(x) = atanh(|x|)/|x| x,  exp0(v) = tanh(|v|)/|v| v,
// and the butterfly always pairs adjacent elements (2k,2k+1), acting as
// [[a,b],[-b,a]] = complex multiply by (a - ib). The whole stack is one
// complex W_k per pair (512 values), and
//   |butterfly(u)|^2 = s1^2 * sum_k |W_k|^2 (x_{2k}^2 + x_{2k+1}^2).
//
// Each CTA builds sW once (params batch-loaded coalesced into smem first —
// no dependent global chain, unlike the failed R5 fused version), then
// persists: warp-per-row, grid-stride over rows, shuffle-only reduction.
__global__ void __launch_bounds__(256)
hyper_butterfly_persistent(const float* __restrict__ x,
                           const float* __restrict__ params,
                           float* __restrict__ out,
                           int rows) {
    __shared__ float sp[NACTIVE];                  // 8 KB raw params (layers 1..9)
    __shared__ __align__(16) float2 sW[NPAIRS];    // 4 KB composite coefficients

    const int t    = threadIdx.x;
    const int warp = t >> 5;
    const int lane = t & 31;

    // ── Prologue A: coalesced batch-load of active params (one round trip).
#pragma unroll
    for (int j = 0; j < 8; ++j) {
        int i = t + 256 * j;
        if (i < NACTIVE) sp[i] = params[2 * DIM + i];
    }
    __syncthreads();

    // ── Prologue B: compose W per pair; thread t does pairs t and t+256.
#pragma unroll
    for (int h = 0; h < 2; ++h) {
        const int k = t + h * 256;
        float A = 1.0f, B = 0.0f;
        int off = 0;
#pragma unroll
        for (int l = 1; l < NLAYER; ++l) {
            const int blk = k >> (l - 1);
            const float a = sp[off + 2 * blk];
            const float b = sp[off + 2 * blk + 1];
            const float nA = A * a + B * b;        // (A+iB)*(a-ib)
            const float nB = B * a - A * b;
            A = nA; B = nB;
            off += 2 * (DIM >> l);
        }
        sW[k] = make_float2(A, B);
    }
    __syncthreads();

    const float4* __restrict__ sW4 = reinterpret_cast<const float4*>(sW);
    const int stride = gridDim.x << 3;             // total warps

    // ── Persistent row loop: identical body to the proven 40.8us kernel,
    //    with W served from smem (conflict-free LDS.128).
    for (int row = (blockIdx.x << 3) + warp; row < rows; row += stride) {
        const float4* __restrict__ xr = reinterpret_cast<const float4*>(x + (size_t)row * DIM);
        float4* __restrict__ orow     = reinterpret_cast<float4*>(out + (size_t)row * DIM);

        // Front-batched loads (MLP=8); ||x||^2 partial needs no W.
        float4 xv[8];
#pragma unroll
        for (int j = 0; j < 8; ++j) xv[j] = xr[lane + 32 * j];

        float r0 = 0.0f, r1 = 0.0f;
#pragma unroll
        for (int j = 0; j < 8; ++j) {
            const float4 w = sW4[lane + 32 * j];
            const float q0 = xv[j].x * xv[j].x + xv[j].y * xv[j].y;
            const float q1 = xv[j].z * xv[j].z + xv[j].w * xv[j].w;
            r0 += q0 + q1;
            r1 += (w.x * w.x + w.y * w.y) * q0
                + (w.z * w.z + w.w * w.w) * q1;
        }

        // Warp butterfly reduce both sums; every lane gets the totals.
#pragma unroll
        for (int o = 16; o; o >>= 1) {
            r0 += __shfl_xor_sync(0xffffffffu, r0, o);
            r1 += __shfl_xor_sync(0xffffffffu, r1, o);
        }

        const float n  = sqrtf(r0);
        const float s1 = atanhf(n) / fmaxf(n, 1e-12f);
        const float m  = s1 * sqrtf(r1);
        const float s  = s1 * tanhf(m) / fmaxf(m, 1e-12f);

        // Rotate, scale, store.
#pragma unroll
        for (int j = 0; j < 8; ++j) {
            const float4 w = sW4[lane + 32 * j];
            float4 o4;
            o4.x = s * (w.x * xv[j].x - w.y * xv[j].y);
            o4.y = s * (w.x * xv[j].y + w.y * xv[j].x);
            o4.z = s * (w.z * xv[j].z - w.w * xv[j].w);
            o4.w = s * (w.z * xv[j].w + w.w * xv[j].z);
            orow[lane + 32 * j] = o4;
        }
    }
}

extern "C" void kernel_launch(void* const* d_in, const int* in_sizes, int n_in,
                              void* d_out, int out_size) {
    const float* x      = (const float*)d_in[0];
    const float* params = (const float*)d_in[1];
    float* out          = (float*)d_out;

    const int rows = in_sizes[0] / DIM;   // 32768
    hyper_butterfly_persistent<<<CTAS, 256>>>(x, params, out, rows);
}